// round 4
// baseline (speedup 1.0000x reference)
#include <cuda_runtime.h>
#include <cuda_fp16.h>
#include <mma.h>
#include <math.h>

using namespace nvcuda;

#define NN 100000
#define DD 128
#define EE 1600000
#define BB 100000

// ---------------- scratch (no allocations allowed) ----------------
__device__ __align__(16) __half g_tmph[(size_t)NN * DD]; // dinv-scaled GEMM out (fp16)
__device__ __align__(16) float  g_h[(size_t)NN * DD];    // layer output / encoding
__device__ float  g_dinv[NN];
__device__ int    g_deg[NN];
__device__ int    g_rowptr[NN + 1];
__device__ int    g_cursor[NN];
__device__ int    g_col[EE];
__device__ int    g_bsum[128];
__device__ int    g_boff[128];
__device__ double g_acc[8];                 // [bce_s, cu_s, ci_s, bce_t, cu_t, ci_t]

// ---------------- degree / CSR build ----------------
__global__ void k_zero(int zero_acc) {
    int i = blockIdx.x * blockDim.x + threadIdx.x;
    if (i < NN) g_deg[i] = 0;
    if (zero_acc && i < 8) g_acc[i] = 0.0;
}

__global__ void k_deg(const int* __restrict__ dst) {
    int e = blockIdx.x * blockDim.x + threadIdx.x;
    if (e < EE) atomicAdd(&g_deg[dst[e]], 1);
}

// phase 1: per-block (1024) exclusive scan; local prefix -> rowptr, block total -> bsum
__global__ void k_scan1() {
    __shared__ int s_warp[32];
    int tid = threadIdx.x;
    int lane = tid & 31, wid = tid >> 5;
    int i = blockIdx.x * 1024 + tid;
    int v = (i < NN) ? g_deg[i] : 0;
    int x = v;
#pragma unroll
    for (int o = 1; o < 32; o <<= 1) {
        int y = __shfl_up_sync(0xffffffffu, x, o);
        if (lane >= o) x += y;
    }
    if (lane == 31) s_warp[wid] = x;
    __syncthreads();
    if (wid == 0) {
        int w = s_warp[lane];
#pragma unroll
        for (int o = 1; o < 32; o <<= 1) {
            int y = __shfl_up_sync(0xffffffffu, w, o);
            if (lane >= o) w += y;
        }
        s_warp[lane] = w;
    }
    __syncthreads();
    int excl = (wid ? s_warp[wid - 1] : 0) + x - v;
    if (i < NN) g_rowptr[i] = excl;
    if (tid == 1023) g_bsum[blockIdx.x] = s_warp[31];
}

// phase 2: single warp scans the block sums
__global__ void k_scan2(int nblk) {
    int lane = threadIdx.x;
    int carry = 0;
    for (int base = 0; base < nblk; base += 32) {
        int idx = base + lane;
        int v = (idx < nblk) ? g_bsum[idx] : 0;
        int x = v;
#pragma unroll
        for (int o = 1; o < 32; o <<= 1) {
            int y = __shfl_up_sync(0xffffffffu, x, o);
            if (lane >= o) x += y;
        }
        if (idx < nblk) g_boff[idx] = carry + x - v;
        carry += __shfl_sync(0xffffffffu, x, 31);
    }
    if (lane == 0) g_rowptr[NN] = carry;
}

// phase 3: add block offsets; init cursor + dinv
__global__ void k_scan3() {
    int i = blockIdx.x * blockDim.x + threadIdx.x;
    if (i < NN) {
        int r = g_rowptr[i] + g_boff[i >> 10];
        g_rowptr[i] = r;
        g_cursor[i] = r;
        g_dinv[i] = rsqrtf((float)g_deg[i] + 1.0f);  // +1 = self loop
    }
}

__global__ void k_fill(const int* __restrict__ src, const int* __restrict__ dst) {
    int e = blockIdx.x * blockDim.x + threadIdx.x;
    if (e < EE) {
        int pos = atomicAdd(&g_cursor[dst[e]], 1);
        g_col[pos] = src[e];
    }
}

// ---------------- gather aggregation ------------------------------------
// tmp' rows are pre-scaled by dinv[row] (done in GEMM epilogue), fp16.
// out[i] = b + dinv_i * (tmp'[i] + sum_j tmp'[j])
__device__ __forceinline__ void acc_row(const uint2* __restrict__ t2, int row, int lane,
                                        float4& acc) {
    uint2 u = t2[row * 32 + lane];
    float2 fa = __half22float2(*(__half2*)&u.x);
    float2 fb = __half22float2(*(__half2*)&u.y);
    acc.x += fa.x; acc.y += fa.y; acc.z += fb.x; acc.w += fb.y;
}

__global__ __launch_bounds__(256) void k_gather(const __half* __restrict__ tmp,
                                                const float* __restrict__ bias,
                                                float* __restrict__ out) {
    int node = blockIdx.x * 8 + (threadIdx.x >> 5);
    int lane = threadIdx.x & 31;
    if (node >= NN) return;
    int beg = g_rowptr[node];
    int end = g_rowptr[node + 1];
    const uint2* t2 = (const uint2*)tmp;
    float4 acc = make_float4(0.f, 0.f, 0.f, 0.f);
    for (int base = beg; base < end; base += 32) {
        int n = min(32, end - base);
        int s = (lane < n) ? g_col[base + lane] : 0;
        int i = 0;
        for (; i + 4 <= n; i += 4) {
            int a = __shfl_sync(0xffffffffu, s, i);
            int b = __shfl_sync(0xffffffffu, s, i + 1);
            int c = __shfl_sync(0xffffffffu, s, i + 2);
            int d = __shfl_sync(0xffffffffu, s, i + 3);
            acc_row(t2, a, lane, acc);
            acc_row(t2, b, lane, acc);
            acc_row(t2, c, lane, acc);
            acc_row(t2, d, lane, acc);
        }
        for (; i < n; i++) {
            int a = __shfl_sync(0xffffffffu, s, i);
            acc_row(t2, a, lane, acc);
        }
    }
    acc_row(t2, node, lane, acc);   // self-loop term (tmp' already dinv-scaled)
    float di = g_dinv[node];
    float4 b = ((const float4*)bias)[lane];
    float4 o;
    o.x = fmaf(di, acc.x, b.x);
    o.y = fmaf(di, acc.y, b.y);
    o.z = fmaf(di, acc.z, b.z);
    o.w = fmaf(di, acc.w, b.w);
    ((float4*)out)[node * 32 + lane] = o;
}

// ------- tensor-core GEMM: C_half[r,:] = dinv[r] * ((relu?)A[r,:] @ W) ----
// block = 128x128 tile, 8 warps (4x2), warp = 32x64, wmma 16x16x16 fp16->fp32
#define LDH 136   // half stride (pad 8)
#define LDC 132   // float stride (pad 4)
#define GEMM_SMEM (2 * 128 * LDH * (int)sizeof(__half))   // 69632; sC (128*LDC*4=67584) reuses it

template <bool RELU>
__global__ __launch_bounds__(256) void k_gemm(const float* __restrict__ A,
                                              const float* __restrict__ W,
                                              __half* __restrict__ C) {
    extern __shared__ char smem[];
    __half* sA = (__half*)smem;                               // 128 x LDH
    __half* sW = (__half*)(smem + 128 * LDH * sizeof(__half)); // 128 x LDH
    float* sC = (float*)smem;                                  // 128 x LDC (reused)
    int tid = threadIdx.x;
    int r0 = blockIdx.x * 128;

    // load W (fp32 -> fp16)
    for (int q = tid; q < 128 * 32; q += 256) {
        int row = q >> 5, c4 = (q & 31) << 2;
        float4 w = *(const float4*)&W[row * DD + c4];
        *(__half2*)&sW[row * LDH + c4] = __floats2half2_rn(w.x, w.y);
        *(__half2*)&sW[row * LDH + c4 + 2] = __floats2half2_rn(w.z, w.w);
    }
    // load A tile (fp32 -> fp16, optional relu)
    for (int q = tid; q < 128 * 32; q += 256) {
        int row = q >> 5, c4 = (q & 31) << 2;
        int gr = r0 + row;
        float4 a = make_float4(0.f, 0.f, 0.f, 0.f);
        if (gr < NN) a = *(const float4*)&A[(size_t)gr * DD + c4];
        if (RELU) {
            a.x = fmaxf(a.x, 0.f); a.y = fmaxf(a.y, 0.f);
            a.z = fmaxf(a.z, 0.f); a.w = fmaxf(a.w, 0.f);
        }
        *(__half2*)&sA[row * LDH + c4] = __floats2half2_rn(a.x, a.y);
        *(__half2*)&sA[row * LDH + c4 + 2] = __floats2half2_rn(a.z, a.w);
    }
    __syncthreads();

    int wid = tid >> 5;
    int wr = wid >> 1;       // 0..3 : row group of 32
    int wc = wid & 1;        // 0..1 : col group of 64

    wmma::fragment<wmma::accumulator, 16, 16, 16, float> acc[2][4];
#pragma unroll
    for (int m = 0; m < 2; m++)
#pragma unroll
        for (int n = 0; n < 4; n++) wmma::fill_fragment(acc[m][n], 0.f);

#pragma unroll
    for (int k = 0; k < 8; k++) {
        wmma::fragment<wmma::matrix_a, 16, 16, 16, __half, wmma::row_major> af[2];
#pragma unroll
        for (int m = 0; m < 2; m++)
            wmma::load_matrix_sync(af[m], &sA[(wr * 32 + m * 16) * LDH + k * 16], LDH);
#pragma unroll
        for (int n = 0; n < 4; n++) {
            wmma::fragment<wmma::matrix_b, 16, 16, 16, __half, wmma::row_major> bf;
            wmma::load_matrix_sync(bf, &sW[(k * 16) * LDH + wc * 64 + n * 16], LDH);
#pragma unroll
            for (int m = 0; m < 2; m++)
                wmma::mma_sync(acc[m][n], af[m], bf, acc[m][n]);
        }
    }
    __syncthreads();   // done reading sA/sW; reuse as sC

#pragma unroll
    for (int m = 0; m < 2; m++)
#pragma unroll
        for (int n = 0; n < 4; n++)
            wmma::store_matrix_sync(&sC[(wr * 32 + m * 16) * LDC + wc * 64 + n * 16],
                                    acc[m][n], LDC, wmma::mem_row_major);
    __syncthreads();

    // epilogue: scale by dinv[row], emit fp16
    for (int q = tid; q < 128 * 32; q += 256) {
        int row = q >> 5, c4 = (q & 31) << 2;
        int gr = r0 + row;
        if (gr < NN) {
            float di = g_dinv[gr];
            float4 v = *(float4*)&sC[row * LDC + c4];
            uint2 u;
            __half2 h;
            h = __floats2half2_rn(v.x * di, v.y * di); u.x = *(unsigned*)&h;
            h = __floats2half2_rn(v.z * di, v.w * di); u.y = *(unsigned*)&h;
            *(uint2*)&C[(size_t)gr * DD + c4] = u;
        }
    }
}

// ---------------- fused loss: one warp per (user,item) pair ----------------
__device__ __forceinline__ float dot4(float4 a, float4 b) {
    return a.x * b.x + a.y * b.y + a.z * b.z + a.w * b.w;
}

__global__ void k_loss(const float* __restrict__ enc,
                       const int* __restrict__ user, const int* __restrict__ item,
                       const int* __restrict__ labels,
                       const float* __restrict__ clsW, const float* __restrict__ clsB,
                       const float* __restrict__ duW, const float* __restrict__ duB,
                       const float* __restrict__ diW, const float* __restrict__ diB,
                       const int* __restrict__ numUser, int accBase) {
    __shared__ float sb[8], su[8], si[8];
    int tid = threadIdx.x;
    int wid = tid >> 5, lane = tid & 31;
    int b = blockIdx.x * 8 + wid;
    float bce = 0.f, cu = 0.f, ci = 0.f;
    if (b < BB) {
        int nu = numUser ? numUser[0] : 50000;
        int u = user[b];
        int it = item[b] + nu;
        float4 uf = ((const float4*)enc)[u * 32 + lane];
        float4 vf = ((const float4*)enc)[it * 32 + lane];
        float4 cwu = ((const float4*)clsW)[lane];
        float4 cwi = ((const float4*)clsW)[32 + lane];
        float4 dw = ((const float4*)duW)[lane];
        float4 iw = ((const float4*)diW)[lane];
        float z = dot4(uf, cwu) + dot4(vf, cwi);
        float zu = dot4(uf, dw);
        float zi = dot4(vf, iw);
#pragma unroll
        for (int o = 16; o; o >>= 1) {
            z  += __shfl_xor_sync(0xffffffffu, z, o);
            zu += __shfl_xor_sync(0xffffffffu, zu, o);
            zi += __shfl_xor_sync(0xffffffffu, zi, o);
        }
        z += clsB[0];
        zu += duB[0];
        zi += diB[0];
        float y = (float)labels[b];
        float sp_pos = log1pf(expf(-fabsf(z))) + fmaxf(z, 0.f);  // softplus(z)
        float sp_neg = sp_pos - z;                               // softplus(-z)
        bce = y * sp_neg + (1.f - y) * sp_pos;
        cu = 1.f / (1.f + expf(-zu));
        ci = 1.f / (1.f + expf(-zi));
    }
    if (lane == 0) { sb[wid] = bce; su[wid] = cu; si[wid] = ci; }
    __syncthreads();
    if (tid == 0) {
        float B_ = 0.f, U = 0.f, I = 0.f;
#pragma unroll
        for (int i = 0; i < 8; i++) { B_ += sb[i]; U += su[i]; I += si[i]; }
        atomicAdd(&g_acc[accBase + 0], (double)B_);
        atomicAdd(&g_acc[accBase + 1], (double)U);
        atomicAdd(&g_acc[accBase + 2], (double)I);
    }
}

__global__ void k_final(float* out) {
    double invB = 1.0 / (double)BB;
    double clf = (g_acc[0] + g_acc[3]) * invB;
    double dom = fabs(g_acc[1] - g_acc[4]) * invB + fabs(g_acc[2] - g_acc[5]) * invB;
    out[0] = (float)(clf + dom);
}

// ---------------- launch ----------------
extern "C" void kernel_launch(void* const* d_in, const int* in_sizes, int n_in,
                              void* d_out, int out_size) {
    const float* feats_s = (const float*)d_in[0];
    const float* feats_t = (const float*)d_in[1];
    const float* W1 = (const float*)d_in[2];
    const float* b1 = (const float*)d_in[3];
    const float* W2 = (const float*)d_in[4];
    const float* b2 = (const float*)d_in[5];
    const float* clsW = (const float*)d_in[6];
    const float* clsB = (const float*)d_in[7];
    const float* duW = (const float*)d_in[8];
    const float* duB = (const float*)d_in[9];
    const float* diW = (const float*)d_in[10];
    const float* diB = (const float*)d_in[11];
    const int* es[2] = {(const int*)d_in[12], (const int*)d_in[14]};
    const int* ed[2] = {(const int*)d_in[13], (const int*)d_in[15]};
    const int* user[2] = {(const int*)d_in[16], (const int*)d_in[19]};
    const int* item[2] = {(const int*)d_in[17], (const int*)d_in[20]};
    const int* lab[2]  = {(const int*)d_in[18], (const int*)d_in[21]};
    const int* nu[2]   = {(n_in > 22) ? (const int*)d_in[22] : (const int*)0,
                          (n_in > 23) ? (const int*)d_in[23] : (const int*)0};
    const float* feats[2] = {feats_s, feats_t};
    float* out = (float*)d_out;

    __half* tmp; float* h;
    cudaGetSymbolAddress((void**)&tmp, g_tmph);
    cudaGetSymbolAddress((void**)&h, g_h);

    cudaFuncSetAttribute(k_gemm<false>, cudaFuncAttributeMaxDynamicSharedMemorySize, GEMM_SMEM);
    cudaFuncSetAttribute(k_gemm<true>, cudaFuncAttributeMaxDynamicSharedMemorySize, GEMM_SMEM);

    const int TB = 256;
    const int NBLK = (NN + 1023) / 1024;   // 98
    for (int dom = 0; dom < 2; dom++) {
        // CSR build (by dst) + dinv
        k_zero<<<(NN + TB - 1) / TB, TB>>>(dom == 0 ? 1 : 0);
        k_deg<<<(EE + TB - 1) / TB, TB>>>(ed[dom]);
        k_scan1<<<NBLK, 1024>>>();
        k_scan2<<<1, 32>>>(NBLK);
        k_scan3<<<(NN + TB - 1) / TB, TB>>>();
        k_fill<<<(EE + TB - 1) / TB, TB>>>(es[dom], ed[dom]);

        // layer 1
        k_gemm<false><<<(NN + 127) / 128, 256, GEMM_SMEM>>>(feats[dom], W1, tmp);
        k_gather<<<(NN + 7) / 8, 256>>>(tmp, b1, h);

        // layer 2 (relu folded into GEMM A-load)
        k_gemm<true><<<(NN + 127) / 128, 256, GEMM_SMEM>>>(h, W2, tmp);
        k_gather<<<(NN + 7) / 8, 256>>>(tmp, b2, h);

        // losses for this domain
        k_loss<<<(BB + 7) / 8, 256>>>(h, user[dom], item[dom], lab[dom],
                                      clsW, clsB, duW, duB, diW, diB,
                                      nu[dom], dom * 3);
    }
    k_final<<<1, 1>>>(out);
}

// round 5
// speedup vs baseline: 1.5886x; 1.5886x over previous
#include <cuda_runtime.h>
#include <cuda_fp16.h>
#include <math.h>

#define NN 100000
#define DD 128
#define EE 1600000
#define BB 100000

// ---------------- scratch, double-buffered per domain (no allocations) ------
__device__ __align__(16) __half g_tmph[2][(size_t)NN * DD]; // dinv-scaled GEMM out
__device__ __align__(16) float  g_h[2][(size_t)NN * DD];    // layer output / encoding
__device__ float  g_dinv[2][NN];
__device__ int    g_deg[2][NN];
__device__ int    g_rowptr[2][NN + 1];
__device__ int    g_cursor[2][NN];
__device__ int    g_col[2][EE];
__device__ int    g_bsum[2][128];
__device__ int    g_boff[2][128];
__device__ double g_acc[8];   // [bce_s, cu_s, ci_s, _, bce_t, cu_t, ci_t, _] -> bases 0,3

// ---------------- tiny init ----------------
__global__ void k_zero_acc() {
    int i = threadIdx.x;
    if (i < 8) g_acc[i] = 0.0;
}

__global__ void k_zero_deg(int* __restrict__ deg) {
    int i = blockIdx.x * blockDim.x + threadIdx.x;
    if (i < NN) deg[i] = 0;
}

__global__ void k_deg(const int* __restrict__ dst, int* __restrict__ deg) {
    int e = blockIdx.x * blockDim.x + threadIdx.x;
    if (e < EE) atomicAdd(&deg[dst[e]], 1);
}

__global__ void k_dinv(const int* __restrict__ deg, float* __restrict__ dinv) {
    int i = blockIdx.x * blockDim.x + threadIdx.x;
    if (i < NN) dinv[i] = rsqrtf((float)deg[i] + 1.0f);  // +1 = self loop
}

// phase 1: per-block (1024) exclusive scan; local prefix -> rowptr, block total -> bsum
__global__ void k_scan1(const int* __restrict__ deg, int* __restrict__ rowptr,
                        int* __restrict__ bsum) {
    __shared__ int s_warp[32];
    int tid = threadIdx.x;
    int lane = tid & 31, wid = tid >> 5;
    int i = blockIdx.x * 1024 + tid;
    int v = (i < NN) ? deg[i] : 0;
    int x = v;
#pragma unroll
    for (int o = 1; o < 32; o <<= 1) {
        int y = __shfl_up_sync(0xffffffffu, x, o);
        if (lane >= o) x += y;
    }
    if (lane == 31) s_warp[wid] = x;
    __syncthreads();
    if (wid == 0) {
        int w = s_warp[lane];
#pragma unroll
        for (int o = 1; o < 32; o <<= 1) {
            int y = __shfl_up_sync(0xffffffffu, w, o);
            if (lane >= o) w += y;
        }
        s_warp[lane] = w;
    }
    __syncthreads();
    int excl = (wid ? s_warp[wid - 1] : 0) + x - v;
    if (i < NN) rowptr[i] = excl;
    if (tid == 1023) bsum[blockIdx.x] = s_warp[31];
}

// phase 2: single warp scans the block sums
__global__ void k_scan2(const int* __restrict__ bsum, int* __restrict__ boff,
                        int* __restrict__ rowptr, int nblk) {
    int lane = threadIdx.x;
    int carry = 0;
    for (int base = 0; base < nblk; base += 32) {
        int idx = base + lane;
        int v = (idx < nblk) ? bsum[idx] : 0;
        int x = v;
#pragma unroll
        for (int o = 1; o < 32; o <<= 1) {
            int y = __shfl_up_sync(0xffffffffu, x, o);
            if (lane >= o) x += y;
        }
        if (idx < nblk) boff[idx] = carry + x - v;
        carry += __shfl_sync(0xffffffffu, x, 31);
    }
    if (lane == 0) rowptr[NN] = carry;
}

// phase 3: add block offsets; init cursor
__global__ void k_scan3(int* __restrict__ rowptr, const int* __restrict__ boff,
                        int* __restrict__ cursor) {
    int i = blockIdx.x * blockDim.x + threadIdx.x;
    if (i < NN) {
        int r = rowptr[i] + boff[i >> 10];
        rowptr[i] = r;
        cursor[i] = r;
    }
}

__global__ void k_fill(const int* __restrict__ src, const int* __restrict__ dst,
                       int* __restrict__ cursor, int* __restrict__ col) {
    int e = blockIdx.x * blockDim.x + threadIdx.x;
    if (e < EE) {
        int pos = atomicAdd(&cursor[dst[e]], 1);
        col[pos] = src[e];
    }
}

// ---------------- gather aggregation ------------------------------------
// tmp' rows are pre-scaled by dinv[row] (done in GEMM epilogue), fp16.
// out[i] = b + dinv_i * (tmp'[i] + sum_j tmp'[j])
__device__ __forceinline__ void acc_row(const uint2* __restrict__ t2, int row, int lane,
                                        float4& acc) {
    uint2 u = t2[row * 32 + lane];
    float2 fa = __half22float2(*(__half2*)&u.x);
    float2 fb = __half22float2(*(__half2*)&u.y);
    acc.x += fa.x; acc.y += fa.y; acc.z += fb.x; acc.w += fb.y;
}

__global__ __launch_bounds__(256) void k_gather(const __half* __restrict__ tmp,
                                                const float* __restrict__ bias,
                                                float* __restrict__ out,
                                                const int* __restrict__ rowptr,
                                                const int* __restrict__ col,
                                                const float* __restrict__ dinv) {
    int node = blockIdx.x * 8 + (threadIdx.x >> 5);
    int lane = threadIdx.x & 31;
    if (node >= NN) return;
    int beg = rowptr[node];
    int end = rowptr[node + 1];
    const uint2* t2 = (const uint2*)tmp;
    float4 acc = make_float4(0.f, 0.f, 0.f, 0.f);
    for (int base = beg; base < end; base += 32) {
        int n = min(32, end - base);
        int s = (lane < n) ? col[base + lane] : 0;
        int i = 0;
        for (; i + 4 <= n; i += 4) {
            int a = __shfl_sync(0xffffffffu, s, i);
            int b = __shfl_sync(0xffffffffu, s, i + 1);
            int c = __shfl_sync(0xffffffffu, s, i + 2);
            int d = __shfl_sync(0xffffffffu, s, i + 3);
            acc_row(t2, a, lane, acc);
            acc_row(t2, b, lane, acc);
            acc_row(t2, c, lane, acc);
            acc_row(t2, d, lane, acc);
        }
        for (; i < n; i++) {
            int a = __shfl_sync(0xffffffffu, s, i);
            acc_row(t2, a, lane, acc);
        }
    }
    acc_row(t2, node, lane, acc);   // self-loop term (tmp' already dinv-scaled)
    float di = dinv[node];
    float4 b = ((const float4*)bias)[lane];
    float4 o;
    o.x = fmaf(di, acc.x, b.x);
    o.y = fmaf(di, acc.y, b.y);
    o.z = fmaf(di, acc.z, b.z);
    o.w = fmaf(di, acc.w, b.w);
    ((float4*)out)[node * 32 + lane] = o;
}

// ------- GEMM (R3-proven FFMA): C_half[r,:] = dinv[r] * ((relu?)A[r,:] @ W) --
template <bool RELU>
__global__ __launch_bounds__(256, 2) void k_gemm(const float* __restrict__ A,
                                                 const float* __restrict__ W,
                                                 __half* __restrict__ C,
                                                 const float* __restrict__ dinv) {
    __shared__ float sW[16 * 128];
    __shared__ float sA[16 * 132];
    int tid = threadIdx.x;
    int r0 = blockIdx.x * 128;
    int tx = tid & 15, ty = tid >> 4;

    float acc[8][8];
#pragma unroll
    for (int m = 0; m < 8; m++)
#pragma unroll
        for (int n = 0; n < 8; n++) acc[m][n] = 0.f;

    for (int kk = 0; kk < DD; kk += 16) {
        __syncthreads();
#pragma unroll
        for (int i = 0; i < 2; i++) {
            int q = tid + 256 * i;
            int row = q >> 2;
            int c4 = (q & 3) << 2;
            int gr = r0 + row;
            float4 a = make_float4(0.f, 0.f, 0.f, 0.f);
            if (gr < NN) a = *(const float4*)&A[(size_t)gr * DD + kk + c4];
            if (RELU) {
                a.x = fmaxf(a.x, 0.f); a.y = fmaxf(a.y, 0.f);
                a.z = fmaxf(a.z, 0.f); a.w = fmaxf(a.w, 0.f);
            }
            sA[(c4 + 0) * 132 + row] = a.x;
            sA[(c4 + 1) * 132 + row] = a.y;
            sA[(c4 + 2) * 132 + row] = a.z;
            sA[(c4 + 3) * 132 + row] = a.w;
        }
#pragma unroll
        for (int i = 0; i < 2; i++) {
            int q = tid + 256 * i;
            int kr = q >> 5;
            int c4 = (q & 31) << 2;
            *(float4*)&sW[kr * 128 + c4] = *(const float4*)&W[(size_t)(kk + kr) * DD + c4];
        }
        __syncthreads();
#pragma unroll
        for (int k2 = 0; k2 < 16; k2++) {
            float4 a0 = *(float4*)&sA[k2 * 132 + ty * 8];
            float4 a1 = *(float4*)&sA[k2 * 132 + ty * 8 + 4];
            const float* wr = &sW[k2 * 128];
            float4 w0 = *(const float4*)&wr[tx * 4];
            float4 w1 = *(const float4*)&wr[64 + tx * 4];
            float av[8] = {a0.x, a0.y, a0.z, a0.w, a1.x, a1.y, a1.z, a1.w};
            float wv[8] = {w0.x, w0.y, w0.z, w0.w, w1.x, w1.y, w1.z, w1.w};
#pragma unroll
            for (int m = 0; m < 8; m++)
#pragma unroll
                for (int n = 0; n < 8; n++)
                    acc[m][n] = fmaf(av[m], wv[n], acc[m][n]);
        }
    }
#pragma unroll
    for (int m = 0; m < 8; m++) {
        int gr = r0 + ty * 8 + m;
        if (gr < NN) {
            float di = dinv[gr];
            uint2 u0, u1;
            __half2 h;
            h = __floats2half2_rn(acc[m][0] * di, acc[m][1] * di); u0.x = *(unsigned*)&h;
            h = __floats2half2_rn(acc[m][2] * di, acc[m][3] * di); u0.y = *(unsigned*)&h;
            h = __floats2half2_rn(acc[m][4] * di, acc[m][5] * di); u1.x = *(unsigned*)&h;
            h = __floats2half2_rn(acc[m][6] * di, acc[m][7] * di); u1.y = *(unsigned*)&h;
            *(uint2*)&C[(size_t)gr * DD + tx * 4] = u0;
            *(uint2*)&C[(size_t)gr * DD + 64 + tx * 4] = u1;
        }
    }
}

// ---------------- fused loss: one warp per (user,item) pair ----------------
__device__ __forceinline__ float dot4(float4 a, float4 b) {
    return a.x * b.x + a.y * b.y + a.z * b.z + a.w * b.w;
}

__global__ void k_loss(const float* __restrict__ enc,
                       const int* __restrict__ user, const int* __restrict__ item,
                       const int* __restrict__ labels,
                       const float* __restrict__ clsW, const float* __restrict__ clsB,
                       const float* __restrict__ duW, const float* __restrict__ duB,
                       const float* __restrict__ diW, const float* __restrict__ diB,
                       const int* __restrict__ numUser, int accBase) {
    __shared__ float sb[8], su[8], si[8];
    int tid = threadIdx.x;
    int wid = tid >> 5, lane = tid & 31;
    int b = blockIdx.x * 8 + wid;
    float bce = 0.f, cu = 0.f, ci = 0.f;
    if (b < BB) {
        int nu = numUser ? numUser[0] : 50000;
        int u = user[b];
        int it = item[b] + nu;
        float4 uf = ((const float4*)enc)[u * 32 + lane];
        float4 vf = ((const float4*)enc)[it * 32 + lane];
        float4 cwu = ((const float4*)clsW)[lane];
        float4 cwi = ((const float4*)clsW)[32 + lane];
        float4 dw = ((const float4*)duW)[lane];
        float4 iw = ((const float4*)diW)[lane];
        float z = dot4(uf, cwu) + dot4(vf, cwi);
        float zu = dot4(uf, dw);
        float zi = dot4(vf, iw);
#pragma unroll
        for (int o = 16; o; o >>= 1) {
            z  += __shfl_xor_sync(0xffffffffu, z, o);
            zu += __shfl_xor_sync(0xffffffffu, zu, o);
            zi += __shfl_xor_sync(0xffffffffu, zi, o);
        }
        z += clsB[0];
        zu += duB[0];
        zi += diB[0];
        float y = (float)labels[b];
        float sp_pos = log1pf(expf(-fabsf(z))) + fmaxf(z, 0.f);  // softplus(z)
        float sp_neg = sp_pos - z;                               // softplus(-z)
        bce = y * sp_neg + (1.f - y) * sp_pos;
        cu = 1.f / (1.f + expf(-zu));
        ci = 1.f / (1.f + expf(-zi));
    }
    if (lane == 0) { sb[wid] = bce; su[wid] = cu; si[wid] = ci; }
    __syncthreads();
    if (tid == 0) {
        float B_ = 0.f, U = 0.f, I = 0.f;
#pragma unroll
        for (int i = 0; i < 8; i++) { B_ += sb[i]; U += su[i]; I += si[i]; }
        atomicAdd(&g_acc[accBase + 0], (double)B_);
        atomicAdd(&g_acc[accBase + 1], (double)U);
        atomicAdd(&g_acc[accBase + 2], (double)I);
    }
}

__global__ void k_final(float* out) {
    double invB = 1.0 / (double)BB;
    double clf = (g_acc[0] + g_acc[3]) * invB;
    double dom = fabs(g_acc[1] - g_acc[4]) * invB + fabs(g_acc[2] - g_acc[5]) * invB;
    out[0] = (float)(clf + dom);
}

// ---------------- launch: two streams, one per domain ----------------
extern "C" void kernel_launch(void* const* d_in, const int* in_sizes, int n_in,
                              void* d_out, int out_size) {
    const float* W1 = (const float*)d_in[2];
    const float* b1 = (const float*)d_in[3];
    const float* W2 = (const float*)d_in[4];
    const float* b2 = (const float*)d_in[5];
    const float* clsW = (const float*)d_in[6];
    const float* clsB = (const float*)d_in[7];
    const float* duW = (const float*)d_in[8];
    const float* duB = (const float*)d_in[9];
    const float* diW = (const float*)d_in[10];
    const float* diB = (const float*)d_in[11];
    const float* feats[2] = {(const float*)d_in[0], (const float*)d_in[1]};
    const int* es[2] = {(const int*)d_in[12], (const int*)d_in[14]};
    const int* ed[2] = {(const int*)d_in[13], (const int*)d_in[15]};
    const int* user[2] = {(const int*)d_in[16], (const int*)d_in[19]};
    const int* item[2] = {(const int*)d_in[17], (const int*)d_in[20]};
    const int* lab[2]  = {(const int*)d_in[18], (const int*)d_in[21]};
    const int* nu[2]   = {(n_in > 22) ? (const int*)d_in[22] : (const int*)0,
                          (n_in > 23) ? (const int*)d_in[23] : (const int*)0};
    float* out = (float*)d_out;

    // lazy host-side stream/event init (no device memory involved)
    static cudaStream_t st[2] = {nullptr, nullptr};
    static cudaEvent_t evRoot = nullptr, evDone[2] = {nullptr, nullptr};
    if (!st[0]) {
        cudaStreamCreateWithFlags(&st[0], cudaStreamNonBlocking);
        cudaStreamCreateWithFlags(&st[1], cudaStreamNonBlocking);
        cudaEventCreateWithFlags(&evRoot, cudaEventDisableTiming);
        cudaEventCreateWithFlags(&evDone[0], cudaEventDisableTiming);
        cudaEventCreateWithFlags(&evDone[1], cudaEventDisableTiming);
    }

    // device symbol base addresses
    __half* tmpB; float* hB; float* dinvB; int *degB, *rowB, *curB, *colB, *bsB, *boB;
    cudaGetSymbolAddress((void**)&tmpB, g_tmph);
    cudaGetSymbolAddress((void**)&hB, g_h);
    cudaGetSymbolAddress((void**)&dinvB, g_dinv);
    cudaGetSymbolAddress((void**)&degB, g_deg);
    cudaGetSymbolAddress((void**)&rowB, g_rowptr);
    cudaGetSymbolAddress((void**)&curB, g_cursor);
    cudaGetSymbolAddress((void**)&colB, g_col);
    cudaGetSymbolAddress((void**)&bsB, g_bsum);
    cudaGetSymbolAddress((void**)&boB, g_boff);

    const int TB = 256;
    const int NBLK = (NN + 1023) / 1024;   // 98

    k_zero_acc<<<1, 32>>>();
    cudaEventRecord(evRoot, 0);

    for (int dom = 0; dom < 2; dom++) {
        cudaStream_t s = st[dom];
        cudaStreamWaitEvent(s, evRoot, 0);
        __half* tmp = tmpB + (size_t)dom * NN * DD;
        float* h = hB + (size_t)dom * NN * DD;
        float* dinv = dinvB + (size_t)dom * NN;
        int* deg = degB + (size_t)dom * NN;
        int* rowptr = rowB + (size_t)dom * (NN + 1);
        int* cursor = curB + (size_t)dom * NN;
        int* col = colB + (size_t)dom * EE;
        int* bsum = bsB + (size_t)dom * 128;
        int* boff = boB + (size_t)dom * 128;

        k_zero_deg<<<(NN + TB - 1) / TB, TB, 0, s>>>(deg);
        k_deg<<<(EE + TB - 1) / TB, TB, 0, s>>>(ed[dom], deg);
        k_dinv<<<(NN + TB - 1) / TB, TB, 0, s>>>(deg, dinv);

        // layer-1 GEMM needs only dinv; runs while CSR finishes? (same stream:
        // ordering only — the cross-domain overlap is the win here)
        k_gemm<false><<<(NN + 127) / 128, 256, 0, s>>>(feats[dom], W1, tmp, dinv);

        k_scan1<<<NBLK, 1024, 0, s>>>(deg, rowptr, bsum);
        k_scan2<<<1, 32, 0, s>>>(bsum, boff, rowptr, NBLK);
        k_scan3<<<(NN + TB - 1) / TB, TB, 0, s>>>(rowptr, boff, cursor);
        k_fill<<<(EE + TB - 1) / TB, TB, 0, s>>>(es[dom], ed[dom], cursor, col);

        k_gather<<<(NN + 7) / 8, 256, 0, s>>>(tmp, b1, h, rowptr, col, dinv);
        k_gemm<true><<<(NN + 127) / 128, 256, 0, s>>>(h, W2, tmp, dinv);
        k_gather<<<(NN + 7) / 8, 256, 0, s>>>(tmp, b2, h, rowptr, col, dinv);

        k_loss<<<(BB + 7) / 8, 256, 0, s>>>(h, user[dom], item[dom], lab[dom],
                                            clsW, clsB, duW, duB, diW, diB,
                                            nu[dom], dom * 3);
        cudaEventRecord(evDone[dom], s);
    }

    cudaStreamWaitEvent(0, evDone[0], 0);
    cudaStreamWaitEvent(0, evDone[1], 0);
    k_final<<<1, 1>>>(out);
}

// round 7
// speedup vs baseline: 1.5957x; 1.0045x over previous
#include <cuda_runtime.h>
#include <cuda_fp16.h>
#include <math.h>

#define NN 100000
#define DD 128
#define EE 1600000
#define BB 100000

// ---------------- scratch, double-buffered per domain (no allocations) ------
__device__ __align__(16) __half g_tmph[2][(size_t)NN * DD]; // dinv-scaled GEMM out
__device__ __align__(16) __half g_h1[2][(size_t)NN * DD];   // relu(layer1 out), fp16
__device__ __align__(16) float  g_h[2][(size_t)NN * DD];    // layer2 out (fp32)
__device__ float  g_dinv[2][NN];
__device__ int    g_deg[2][NN];
__device__ int    g_rowptr[2][NN + 1];
__device__ int    g_cursor[2][NN];
__device__ int    g_col[2][EE];
__device__ int    g_bsum[2][128];
__device__ int    g_boff[2][128];
__device__ double g_acc[8];   // bases 0 (src) and 3 (tgt)

// ---------------- tiny init ----------------
__global__ void k_zero_acc() {
    int i = threadIdx.x;
    if (i < 8) g_acc[i] = 0.0;
}

__global__ void k_zero_deg(int* __restrict__ deg) {
    int i = blockIdx.x * blockDim.x + threadIdx.x;
    if (i < NN) deg[i] = 0;
}

__global__ void k_deg(const int* __restrict__ dst, int* __restrict__ deg) {
    int e4 = blockIdx.x * blockDim.x + threadIdx.x;
    if (e4 < EE / 4) {
        int4 d = ((const int4*)dst)[e4];
        atomicAdd(&deg[d.x], 1);
        atomicAdd(&deg[d.y], 1);
        atomicAdd(&deg[d.z], 1);
        atomicAdd(&deg[d.w], 1);
    }
}

__global__ void k_dinv(const int* __restrict__ deg, float* __restrict__ dinv) {
    int i = blockIdx.x * blockDim.x + threadIdx.x;
    if (i < NN) dinv[i] = rsqrtf((float)deg[i] + 1.0f);  // +1 = self loop
}

// phase 1: per-block (1024) exclusive scan; local prefix -> rowptr, block total -> bsum
__global__ void k_scan1(const int* __restrict__ deg, int* __restrict__ rowptr,
                        int* __restrict__ bsum) {
    __shared__ int s_warp[32];
    int tid = threadIdx.x;
    int lane = tid & 31, wid = tid >> 5;
    int i = blockIdx.x * 1024 + tid;
    int v = (i < NN) ? deg[i] : 0;
    int x = v;
#pragma unroll
    for (int o = 1; o < 32; o <<= 1) {
        int y = __shfl_up_sync(0xffffffffu, x, o);
        if (lane >= o) x += y;
    }
    if (lane == 31) s_warp[wid] = x;
    __syncthreads();
    if (wid == 0) {
        int w = s_warp[lane];
#pragma unroll
        for (int o = 1; o < 32; o <<= 1) {
            int y = __shfl_up_sync(0xffffffffu, w, o);
            if (lane >= o) w += y;
        }
        s_warp[lane] = w;
    }
    __syncthreads();
    int excl = (wid ? s_warp[wid - 1] : 0) + x - v;
    if (i < NN) rowptr[i] = excl;
    if (tid == 1023) bsum[blockIdx.x] = s_warp[31];
}

__global__ void k_scan2(const int* __restrict__ bsum, int* __restrict__ boff,
                        int* __restrict__ rowptr, int nblk) {
    int lane = threadIdx.x;
    int carry = 0;
    for (int base = 0; base < nblk; base += 32) {
        int idx = base + lane;
        int v = (idx < nblk) ? bsum[idx] : 0;
        int x = v;
#pragma unroll
        for (int o = 1; o < 32; o <<= 1) {
            int y = __shfl_up_sync(0xffffffffu, x, o);
            if (lane >= o) x += y;
        }
        if (idx < nblk) boff[idx] = carry + x - v;
        carry += __shfl_sync(0xffffffffu, x, 31);
    }
    if (lane == 0) rowptr[NN] = carry;
}

__global__ void k_scan3(int* __restrict__ rowptr, const int* __restrict__ boff,
                        int* __restrict__ cursor) {
    int i = blockIdx.x * blockDim.x + threadIdx.x;
    if (i < NN) {
        int r = rowptr[i] + boff[i >> 10];
        rowptr[i] = r;
        cursor[i] = r;
    }
}

__global__ void k_fill(const int* __restrict__ src, const int* __restrict__ dst,
                       int* __restrict__ cursor, int* __restrict__ col) {
    int e4 = blockIdx.x * blockDim.x + threadIdx.x;
    if (e4 < EE / 4) {
        int4 s = ((const int4*)src)[e4];
        int4 d = ((const int4*)dst)[e4];
        int p;
        p = atomicAdd(&cursor[d.x], 1); col[p] = s.x;
        p = atomicAdd(&cursor[d.y], 1); col[p] = s.y;
        p = atomicAdd(&cursor[d.z], 1); col[p] = s.z;
        p = atomicAdd(&cursor[d.w], 1); col[p] = s.w;
    }
}

// ---------------- gather aggregation ------------------------------------
// tmp' rows are pre-scaled by dinv[row] (GEMM epilogue), fp16.
// o[i] = b + dinv_i * (tmp'[i] + sum_j tmp'[j])
// HALF_RELU: write relu(o) as fp16 (feeds gemm2); else write o as fp32.
__device__ __forceinline__ void acc_row(const uint2* __restrict__ t2, int row, int lane,
                                        float4& acc) {
    uint2 u = t2[row * 32 + lane];
    float2 fa = __half22float2(*(__half2*)&u.x);
    float2 fb = __half22float2(*(__half2*)&u.y);
    acc.x += fa.x; acc.y += fa.y; acc.z += fb.x; acc.w += fb.y;
}

template <bool HALF_RELU>
__global__ __launch_bounds__(256) void k_gather(const __half* __restrict__ tmp,
                                                const float* __restrict__ bias,
                                                void* __restrict__ outv,
                                                const int* __restrict__ rowptr,
                                                const int* __restrict__ col,
                                                const float* __restrict__ dinv) {
    int node = blockIdx.x * 8 + (threadIdx.x >> 5);
    int lane = threadIdx.x & 31;
    if (node >= NN) return;
    int beg = rowptr[node];
    int end = rowptr[node + 1];
    const uint2* t2 = (const uint2*)tmp;
    float4 acc = make_float4(0.f, 0.f, 0.f, 0.f);
    for (int base = beg; base < end; base += 32) {
        int n = min(32, end - base);
        int s = (lane < n) ? col[base + lane] : 0;
        int i = 0;
        for (; i + 4 <= n; i += 4) {
            int a = __shfl_sync(0xffffffffu, s, i);
            int b = __shfl_sync(0xffffffffu, s, i + 1);
            int c = __shfl_sync(0xffffffffu, s, i + 2);
            int d = __shfl_sync(0xffffffffu, s, i + 3);
            acc_row(t2, a, lane, acc);
            acc_row(t2, b, lane, acc);
            acc_row(t2, c, lane, acc);
            acc_row(t2, d, lane, acc);
        }
        for (; i < n; i++) {
            int a = __shfl_sync(0xffffffffu, s, i);
            acc_row(t2, a, lane, acc);
        }
    }
    acc_row(t2, node, lane, acc);   // self-loop term (tmp' pre-scaled)
    float di = dinv[node];
    float4 b = ((const float4*)bias)[lane];
    float4 o;
    o.x = fmaf(di, acc.x, b.x);
    o.y = fmaf(di, acc.y, b.y);
    o.z = fmaf(di, acc.z, b.z);
    o.w = fmaf(di, acc.w, b.w);
    if (HALF_RELU) {
        o.x = fmaxf(o.x, 0.f); o.y = fmaxf(o.y, 0.f);
        o.z = fmaxf(o.z, 0.f); o.w = fmaxf(o.w, 0.f);
        uint2 u;
        __half2 h;
        h = __floats2half2_rn(o.x, o.y); u.x = *(unsigned*)&h;
        h = __floats2half2_rn(o.z, o.w); u.y = *(unsigned*)&h;
        ((uint2*)outv)[node * 32 + lane] = u;
    } else {
        ((float4*)outv)[node * 32 + lane] = o;
    }
}

// ------- GEMM: C_half[r,:] = dinv[r] * (A[r,:] @ W) ----------------------
// AHALF: A rows are fp16 (layer2); else fp32 (feats). Double-buffered via
// register staging: next chunk's LDGs are in flight during compute.
template <bool AHALF>
__global__ __launch_bounds__(256, 2) void k_gemm(const void* __restrict__ Av,
                                                 const float* __restrict__ W,
                                                 __half* __restrict__ C,
                                                 const float* __restrict__ dinv) {
    __shared__ float sW[16 * 128];
    __shared__ float sA[16 * 132];
    int tid = threadIdx.x;
    int r0 = blockIdx.x * 128;
    int tx = tid & 15, ty = tid >> 4;

    // constant per-thread load mapping
    // A (float path): two (row, c4) slots; A (half path): one (row, c8) slot
    int f_row0 = tid >> 2,            f_c40 = (tid & 3) << 2;
    int f_row1 = (tid + 256) >> 2,    f_c41 = ((tid + 256) & 3) << 2;
    int h_row = tid >> 1,             h_c8 = (tid & 1) << 3;
    // W: two (kr, c4) slots
    int w_kr0 = tid >> 5,             w_c40 = (tid & 31) << 2;
    int w_kr1 = (tid + 256) >> 5,     w_c41 = ((tid + 256) & 31) << 2;

    float a_st[8];
    float4 w_st[2];

    auto load_chunk = [&](int kk) {
        if (AHALF) {
            const __half* Ah = (const __half*)Av;
            int gr = r0 + h_row;
            uint4 u = make_uint4(0u, 0u, 0u, 0u);
            if (gr < NN) u = *(const uint4*)&Ah[(size_t)gr * DD + kk + h_c8];
            float2 f;
            f = __half22float2(*(__half2*)&u.x); a_st[0] = f.x; a_st[1] = f.y;
            f = __half22float2(*(__half2*)&u.y); a_st[2] = f.x; a_st[3] = f.y;
            f = __half22float2(*(__half2*)&u.z); a_st[4] = f.x; a_st[5] = f.y;
            f = __half22float2(*(__half2*)&u.w); a_st[6] = f.x; a_st[7] = f.y;
        } else {
            const float* Af = (const float*)Av;
            int gr0 = r0 + f_row0, gr1 = r0 + f_row1;
            float4 a0 = make_float4(0.f, 0.f, 0.f, 0.f);
            float4 a1 = make_float4(0.f, 0.f, 0.f, 0.f);
            if (gr0 < NN) a0 = *(const float4*)&Af[(size_t)gr0 * DD + kk + f_c40];
            if (gr1 < NN) a1 = *(const float4*)&Af[(size_t)gr1 * DD + kk + f_c41];
            a_st[0] = a0.x; a_st[1] = a0.y; a_st[2] = a0.z; a_st[3] = a0.w;
            a_st[4] = a1.x; a_st[5] = a1.y; a_st[6] = a1.z; a_st[7] = a1.w;
        }
        w_st[0] = *(const float4*)&W[(size_t)(kk + w_kr0) * DD + w_c40];
        w_st[1] = *(const float4*)&W[(size_t)(kk + w_kr1) * DD + w_c41];
    };

    auto store_chunk = [&]() {
        if (AHALF) {
#pragma unroll
            for (int j = 0; j < 8; j++) sA[(h_c8 + j) * 132 + h_row] = a_st[j];
        } else {
#pragma unroll
            for (int j = 0; j < 4; j++) sA[(f_c40 + j) * 132 + f_row0] = a_st[j];
#pragma unroll
            for (int j = 0; j < 4; j++) sA[(f_c41 + j) * 132 + f_row1] = a_st[4 + j];
        }
        *(float4*)&sW[w_kr0 * 128 + w_c40] = w_st[0];
        *(float4*)&sW[w_kr1 * 128 + w_c41] = w_st[1];
    };

    float acc[8][8];
#pragma unroll
    for (int m = 0; m < 8; m++)
#pragma unroll
        for (int n = 0; n < 8; n++) acc[m][n] = 0.f;

    load_chunk(0);
    for (int c = 0; c < 8; c++) {
        __syncthreads();           // previous compute done reading smem
        store_chunk();
        __syncthreads();           // smem ready
        if (c < 7) load_chunk((c + 1) * 16);   // LDGs overlap compute below
#pragma unroll
        for (int k2 = 0; k2 < 16; k2++) {
            float4 a0 = *(float4*)&sA[k2 * 132 + ty * 8];
            float4 a1 = *(float4*)&sA[k2 * 132 + ty * 8 + 4];
            const float* wr = &sW[k2 * 128];
            float4 w0 = *(const float4*)&wr[tx * 4];
            float4 w1 = *(const float4*)&wr[64 + tx * 4];
            float av[8] = {a0.x, a0.y, a0.z, a0.w, a1.x, a1.y, a1.z, a1.w};
            float wv[8] = {w0.x, w0.y, w0.z, w0.w, w1.x, w1.y, w1.z, w1.w};
#pragma unroll
            for (int m = 0; m < 8; m++)
#pragma unroll
                for (int n = 0; n < 8; n++)
                    acc[m][n] = fmaf(av[m], wv[n], acc[m][n]);
        }
    }

#pragma unroll
    for (int m = 0; m < 8; m++) {
        int gr = r0 + ty * 8 + m;
        if (gr < NN) {
            float di = dinv[gr];
            uint2 u0, u1;
            __half2 h;
            h = __floats2half2_rn(acc[m][0] * di, acc[m][1] * di); u0.x = *(unsigned*)&h;
            h = __floats2half2_rn(acc[m][2] * di, acc[m][3] * di); u0.y = *(unsigned*)&h;
            h = __floats2half2_rn(acc[m][4] * di, acc[m][5] * di); u1.x = *(unsigned*)&h;
            h = __floats2half2_rn(acc[m][6] * di, acc[m][7] * di); u1.y = *(unsigned*)&h;
            *(uint2*)&C[(size_t)gr * DD + tx * 4] = u0;
            *(uint2*)&C[(size_t)gr * DD + 64 + tx * 4] = u1;
        }
    }
}

// ---------------- fused loss: one warp per (user,item) pair ----------------
__device__ __forceinline__ float dot4(float4 a, float4 b) {
    return a.x * b.x + a.y * b.y + a.z * b.z + a.w * b.w;
}

__global__ void k_loss(const float* __restrict__ enc,
                       const int* __restrict__ user, const int* __restrict__ item,
                       const int* __restrict__ labels,
                       const float* __restrict__ clsW, const float* __restrict__ clsB,
                       const float* __restrict__ duW, const float* __restrict__ duB,
                       const float* __restrict__ diW, const float* __restrict__ diB,
                       const int* __restrict__ numUser, int accBase) {
    __shared__ float sb[8], su[8], si[8];
    int tid = threadIdx.x;
    int wid = tid >> 5, lane = tid & 31;
    int b = blockIdx.x * 8 + wid;
    float bce = 0.f, cu = 0.f, ci = 0.f;
    if (b < BB) {
        int nu = numUser ? numUser[0] : 50000;
        int u = user[b];
        int it = item[b] + nu;
        float4 uf = ((const float4*)enc)[u * 32 + lane];
        float4 vf = ((const float4*)enc)[it * 32 + lane];
        float4 cwu = ((const float4*)clsW)[lane];
        float4 cwi = ((const float4*)clsW)[32 + lane];
        float4 dw = ((const float4*)duW)[lane];
        float4 iw = ((const float4*)diW)[lane];
        float z = dot4(uf, cwu) + dot4(vf, cwi);
        float zu = dot4(uf, dw);
        float zi = dot4(vf, iw);
#pragma unroll
        for (int o = 16; o; o >>= 1) {
            z  += __shfl_xor_sync(0xffffffffu, z, o);
            zu += __shfl_xor_sync(0xffffffffu, zu, o);
            zi += __shfl_xor_sync(0xffffffffu, zi, o);
        }
        z += clsB[0];
        zu += duB[0];
        zi += diB[0];
        float y = (float)labels[b];
        float sp_pos = log1pf(expf(-fabsf(z))) + fmaxf(z, 0.f);  // softplus(z)
        float sp_neg = sp_pos - z;                               // softplus(-z)
        bce = y * sp_neg + (1.f - y) * sp_pos;
        cu = 1.f / (1.f + expf(-zu));
        ci = 1.f / (1.f + expf(-zi));
    }
    if (lane == 0) { sb[wid] = bce; su[wid] = cu; si[wid] = ci; }
    __syncthreads();
    if (tid == 0) {
        float B_ = 0.f, U = 0.f, I = 0.f;
#pragma unroll
        for (int i = 0; i < 8; i++) { B_ += sb[i]; U += su[i]; I += si[i]; }
        atomicAdd(&g_acc[accBase + 0], (double)B_);
        atomicAdd(&g_acc[accBase + 1], (double)U);
        atomicAdd(&g_acc[accBase + 2], (double)I);
    }
}

__global__ void k_final(float* out) {
    double invB = 1.0 / (double)BB;
    double clf = (g_acc[0] + g_acc[3]) * invB;
    double dom = fabs(g_acc[1] - g_acc[4]) * invB + fabs(g_acc[2] - g_acc[5]) * invB;
    out[0] = (float)(clf + dom);
}

// ---------------- launch: two streams, one per domain (R5 footprint) ------
extern "C" void kernel_launch(void* const* d_in, const int* in_sizes, int n_in,
                              void* d_out, int out_size) {
    const float* W1 = (const float*)d_in[2];
    const float* b1 = (const float*)d_in[3];
    const float* W2 = (const float*)d_in[4];
    const float* b2 = (const float*)d_in[5];
    const float* clsW = (const float*)d_in[6];
    const float* clsB = (const float*)d_in[7];
    const float* duW = (const float*)d_in[8];
    const float* duB = (const float*)d_in[9];
    const float* diW = (const float*)d_in[10];
    const float* diB = (const float*)d_in[11];
    const float* feats[2] = {(const float*)d_in[0], (const float*)d_in[1]};
    const int* es[2] = {(const int*)d_in[12], (const int*)d_in[14]};
    const int* ed[2] = {(const int*)d_in[13], (const int*)d_in[15]};
    const int* user[2] = {(const int*)d_in[16], (const int*)d_in[19]};
    const int* item[2] = {(const int*)d_in[17], (const int*)d_in[20]};
    const int* lab[2]  = {(const int*)d_in[18], (const int*)d_in[21]};
    const int* nu[2]   = {(n_in > 22) ? (const int*)d_in[22] : (const int*)0,
                          (n_in > 23) ? (const int*)d_in[23] : (const int*)0};
    float* out = (float*)d_out;

    static cudaStream_t st[2] = {nullptr, nullptr};
    static cudaEvent_t evRoot = nullptr, evDone[2] = {nullptr, nullptr};
    if (!st[0]) {
        cudaStreamCreateWithFlags(&st[0], cudaStreamNonBlocking);
        cudaStreamCreateWithFlags(&st[1], cudaStreamNonBlocking);
        cudaEventCreateWithFlags(&evRoot, cudaEventDisableTiming);
        cudaEventCreateWithFlags(&evDone[0], cudaEventDisableTiming);
        cudaEventCreateWithFlags(&evDone[1], cudaEventDisableTiming);
    }

    __half* tmpB; __half* h1B; float* hB; float* dinvB;
    int *degB, *rowB, *curB, *colB, *bsB, *boB;
    cudaGetSymbolAddress((void**)&tmpB, g_tmph);
    cudaGetSymbolAddress((void**)&h1B, g_h1);
    cudaGetSymbolAddress((void**)&hB, g_h);
    cudaGetSymbolAddress((void**)&dinvB, g_dinv);
    cudaGetSymbolAddress((void**)&degB, g_deg);
    cudaGetSymbolAddress((void**)&rowB, g_rowptr);
    cudaGetSymbolAddress((void**)&curB, g_cursor);
    cudaGetSymbolAddress((void**)&colB, g_col);
    cudaGetSymbolAddress((void**)&bsB, g_bsum);
    cudaGetSymbolAddress((void**)&boB, g_boff);

    const int TB = 256;
    const int NBLK = (NN + 1023) / 1024;   // 98

    k_zero_acc<<<1, 32>>>();
    cudaEventRecord(evRoot, 0);

    for (int dom = 0; dom < 2; dom++) {
        cudaStream_t s = st[dom];
        cudaStreamWaitEvent(s, evRoot, 0);
        __half* tmp = tmpB + (size_t)dom * NN * DD;
        __half* h1 = h1B + (size_t)dom * NN * DD;
        float* h = hB + (size_t)dom * NN * DD;
        float* dinv = dinvB + (size_t)dom * NN;
        int* deg = degB + (size_t)dom * NN;
        int* rowptr = rowB + (size_t)dom * (NN + 1);
        int* cursor = curB + (size_t)dom * NN;
        int* col = colB + (size_t)dom * EE;
        int* bsum = bsB + (size_t)dom * 128;
        int* boff = boB + (size_t)dom * 128;

        k_zero_deg<<<(NN + TB - 1) / TB, TB, 0, s>>>(deg);
        k_deg<<<(EE / 4 + TB - 1) / TB, TB, 0, s>>>(ed[dom], deg);
        k_dinv<<<(NN + TB - 1) / TB, TB, 0, s>>>(deg, dinv);

        k_gemm<false><<<(NN + 127) / 128, 256, 0, s>>>(feats[dom], W1, tmp, dinv);

        k_scan1<<<NBLK, 1024, 0, s>>>(deg, rowptr, bsum);
        k_scan2<<<1, 32, 0, s>>>(bsum, boff, rowptr, NBLK);
        k_scan3<<<(NN + TB - 1) / TB, TB, 0, s>>>(rowptr, boff, cursor);
        k_fill<<<(EE / 4 + TB - 1) / TB, TB, 0, s>>>(es[dom], ed[dom], cursor, col);

        k_gather<true><<<(NN + 7) / 8, 256, 0, s>>>(tmp, b1, h1, rowptr, col, dinv);
        k_gemm<true><<<(NN + 127) / 128, 256, 0, s>>>(h1, W2, tmp, dinv);
        k_gather<false><<<(NN + 7) / 8, 256, 0, s>>>(tmp, b2, h, rowptr, col, dinv);

        k_loss<<<(BB + 7) / 8, 256, 0, s>>>(h, user[dom], item[dom], lab[dom],
                                            clsW, clsB, duW, duB, diW, diB,
                                            nu[dom], dom * 3);
        cudaEventRecord(evDone[dom], s);
    }

    cudaStreamWaitEvent(0, evDone[0], 0);
    cudaStreamWaitEvent(0, evDone[1], 0);
    k_final<<<1, 1>>>(out);
}